// round 6
// baseline (speedup 1.0000x reference)
#include <cuda_runtime.h>
#include <cuda_fp16.h>
#include <cstdint>
#include <cstddef>

// ----- problem constants -----
#define LSITES  784
#define CHI     128
#define BATCH   1024
#define NCLS    10
#define WROW    264                   // padded k-stride of transposed W (halves)
#define SITE_HALVES (CHI * WROW)      // full site: 33792 halves
#define BC      16                    // samples per cluster slab
#define NLOC    64                    // N columns per CTA (rank half)
#define WHALF_HALVES (NLOC * WROW)    // 16896 halves staged per CTA per site
#define WHALF_BYTES  (WHALF_HALVES * 2)  // 33792 B
#define HROW    132                   // classifier h row stride (floats)
#define AROW    136                   // padded A row stride (halves), K=128
#define ABUF_HALVES (BC * AROW)       // 2176 halves
#define ABUF_BYTES  (ABUF_HALVES * 2) // 4352 B
#define SMEM_A_OFF   (2 * WHALF_BYTES)              // 67584
#define SMEM_MB_OFF  (SMEM_A_OFF + 2 * ABUF_BYTES)  // 76288  [W0,W1,A]
#define SMEM_TOTAL   (SMEM_MB_OFF + 32)             // 76320

// fp16 transposed weights: Wt[site][b][k], k = s*128 + a, row stride WROW
__device__ __half g_Wt[(size_t)LSITES * SITE_HALVES];   // ~50.5 MB static scratch

// ---------------------------------------------------------------------------
// Prepass: W fp32 [n][s][a][b]  ->  fp16 Wt [n][b][k=s*128+a], padded rows
// ---------------------------------------------------------------------------
__global__ void __launch_bounds__(256) prep_kernel(const float* __restrict__ W) {
    extern __shared__ __half sw[];   // [256][132] halves
    const int n   = blockIdx.x;
    const int tid = threadIdx.x;
    const float* Wg = W + (size_t)n * (2 * CHI * CHI);

    for (int i = 0; i < 128; ++i) {
        int e = i * 256 + tid;
        int k = e >> 7;
        int b = e & 127;
        sw[k * 132 + b] = __float2half_rn(Wg[e]);
    }
    __syncthreads();

    const int w    = tid >> 5;
    const int lane = tid & 31;
    for (int r = 0; r < 16; ++r) {
        int b  = w * 16 + r;
        int k0 = lane * 8;
        __align__(16) __half tmp[8];
#pragma unroll
        for (int j = 0; j < 8; ++j) tmp[j] = sw[(k0 + j) * 132 + b];
        *(uint4*)(&g_Wt[((size_t)n * CHI + b) * WROW + k0]) = *(uint4*)tmp;
    }
}

// ---------------------------------------------------------------------------
__device__ __forceinline__ void mbar_wait_cta(uint32_t mbar, uint32_t parity) {
    asm volatile(
        "{\n\t.reg .pred P;\n"
        "W%=:\n\t"
        "mbarrier.try_wait.parity.acquire.cta.shared::cta.b64 P, [%0], %1, 0x989680;\n\t"
        "@!P bra W%=;\n\t}"
        :: "r"(mbar), "r"(parity) : "memory");
}
__device__ __forceinline__ void mbar_wait_cluster(uint32_t mbar, uint32_t parity) {
    asm volatile(
        "{\n\t.reg .pred P;\n"
        "W%=:\n\t"
        "mbarrier.try_wait.parity.acquire.cluster.shared::cta.b64 P, [%0], %1, 0x989680;\n\t"
        "@!P bra W%=;\n\t}"
        :: "r"(mbar), "r"(parity) : "memory");
}

// ---------------------------------------------------------------------------
// Main kernel: 2-CTA cluster N-split, register-resident h, fp16 mma.sync.
// rank r owns output cols [64r, 64r+64); h exchanged via DSMEM every site.
// ---------------------------------------------------------------------------
__global__ void __launch_bounds__(256, 1) __cluster_dims__(2, 1, 1)
mps_kernel(const float* __restrict__ x,
           const float* __restrict__ V,
           float* __restrict__ out) {
    extern __shared__ char smem[];
    __half* Wbuf = (__half*)smem;                   // [2][WHALF_HALVES]
    __half* Abuf = (__half*)(smem + SMEM_A_OFF);    // [2][BC][AROW] fp16(h), full 128 cols
    const uint32_t mb = (uint32_t)__cvta_generic_to_shared(smem + SMEM_MB_OFF);

    const int tid  = threadIdx.x;
    const int rank = blockIdx.x & 1;
    const int slab = blockIdx.x >> 1;
    const int w    = tid >> 5;               // warp 0..7 -> local n8 tile
    const int lane = tid & 31;
    const int g    = lane >> 2;              // 0..7
    const int tg   = lane & 3;               // 0..3
    const int c0g  = rank * NLOC + w * 8 + 2 * tg;   // owned global h column base

    // h register layout (m16n8 acc): rows g,g+8 x cols c0g,c0g+1
    float h[4] = {1.f, 1.f, 1.f, 1.f};

    // init A buffer 0 to fp16(1) (full slab)
    {
        const __half one = __float2half_rn(1.f);
        for (int i = tid; i < ABUF_HALVES; i += 256) Abuf[i] = one;
    }
    if (tid == 0) {
        asm volatile("mbarrier.init.shared.b64 [%0], 1;" :: "r"(mb)      : "memory");
        asm volatile("mbarrier.init.shared.b64 [%0], 1;" :: "r"(mb + 8)  : "memory");
        asm volatile("mbarrier.init.shared.b64 [%0], 1;" :: "r"(mb + 16) : "memory");
    }
    __syncthreads();
    // cluster-wide: barriers initialized before any remote arrive
    asm volatile("barrier.cluster.arrive.aligned;" ::: "memory");
    asm volatile("barrier.cluster.wait.aligned;"   ::: "memory");

    const uint32_t wbuf_s = (uint32_t)__cvta_generic_to_shared(Wbuf);
    const uint32_t abuf_s = (uint32_t)__cvta_generic_to_shared(Abuf);

    // peer (DSMEM) base addresses
    uint32_t abuf_peer, ambar_peer, fh_peer;
    {
        const uint32_t pr = rank ^ 1;
        const uint32_t smem_s = (uint32_t)__cvta_generic_to_shared(smem);
        asm("mapa.shared::cluster.u32 %0, %1, %2;" : "=r"(abuf_peer)  : "r"(abuf_s),  "r"(pr));
        asm("mapa.shared::cluster.u32 %0, %1, %2;" : "=r"(ambar_peer) : "r"(mb + 16), "r"(pr));
        asm("mapa.shared::cluster.u32 %0, %1, %2;" : "=r"(fh_peer)    : "r"(smem_s),  "r"(pr));
    }

    // prologue: stage this rank's half of site 0 into W buffer 0
    const char* wsrc0 = (const char*)(g_Wt + (size_t)rank * WHALF_HALVES);
    if (tid == 0) {
        asm volatile("mbarrier.arrive.expect_tx.shared.b64 _, [%0], %1;"
                     :: "r"(mb), "r"((uint32_t)WHALF_BYTES) : "memory");
        asm volatile(
            "cp.async.bulk.shared::cluster.global.mbarrier::complete_tx::bytes [%0], [%1], %2, [%3];"
            :: "r"(wbuf_s), "l"((const void*)wsrc0), "r"((uint32_t)WHALF_BYTES), "r"(mb)
            : "memory");
    }

    // per-thread x streams: samples slab*16+g and slab*16+g+8, features 0/1
    const int sg0 = slab * BC + g;
    const int sg1 = sg0 + 8;
    const float* px00 = x + ((size_t)sg0 * 2 + 0) * LSITES;
    const float* px01 = x + ((size_t)sg0 * 2 + 1) * LSITES;
    const float* px10 = x + ((size_t)sg1 * 2 + 0) * LSITES;
    const float* px11 = x + ((size_t)sg1 * 2 + 1) * LSITES;
    float cx00 = __ldg(px00), cx01 = __ldg(px01);
    float cx10 = __ldg(px10), cx11 = __ldg(px11);

    // ldmatrix lane addresses
    const uint32_t a_base = abuf_s + (uint32_t)((((lane & 15) * AROW) + ((lane >> 4) * 8)) * 2);
    const int grp = lane >> 3;
    const int r8  = lane & 7;
    // B tiles per x4: (klo,chunk 2j)(khi,2j)(klo,2j+1)(khi,2j+1) of this warp's n8 rows
    const uint32_t b_base = wbuf_s +
        (uint32_t)(((w * 8 + r8) * WROW + (grp & 1) * 8 + ((grp >> 1) & 1) * 16) * 2);

    uint32_t phW0 = 0, phW1 = 0, phA = 0;

    for (int n = 0; n < LSITES; ++n) {
        const int p = n & 1;

        // stage this rank's half of site n+1 into the other W buffer
        if (tid == 0 && n + 1 < LSITES) {
            const uint32_t mnext = mb + (uint32_t)((1 - p) * 8);
            asm volatile("mbarrier.arrive.expect_tx.shared.b64 _, [%0], %1;"
                         :: "r"(mnext), "r"((uint32_t)WHALF_BYTES) : "memory");
            asm volatile(
                "cp.async.bulk.shared::cluster.global.mbarrier::complete_tx::bytes [%0], [%1], %2, [%3];"
                :: "r"(wbuf_s + (uint32_t)((1 - p) * WHALF_BYTES)),
                   "l"((const void*)(wsrc0 + (size_t)(n + 1) * SITE_HALVES * 2)),
                   "r"((uint32_t)WHALF_BYTES), "r"(mnext)
                : "memory");
        }

        // prefetch x for next site
        float nx00 = 0.f, nx01 = 0.f, nx10 = 0.f, nx11 = 0.f;
        if (n + 1 < LSITES) {
            nx00 = __ldg(px00 + n + 1); nx01 = __ldg(px01 + n + 1);
            nx10 = __ldg(px10 + n + 1); nx11 = __ldg(px11 + n + 1);
        }

        // A fragments: 8 k-chunks of fp16(h), shared by both GEMMs
        uint32_t a[8][4];
        {
            const uint32_t ab = a_base + (uint32_t)(p * ABUF_BYTES);
#pragma unroll
            for (int ca = 0; ca < 8; ++ca) {
                asm volatile(
                    "ldmatrix.sync.aligned.m8n8.x4.shared.b16 {%0,%1,%2,%3}, [%4];\n"
                    : "=r"(a[ca][0]), "=r"(a[ca][1]), "=r"(a[ca][2]), "=r"(a[ca][3])
                    : "r"(ab + (uint32_t)(ca * 32)));
            }
        }

        // wait for this site's W half
        mbar_wait_cta(mb + (uint32_t)(p * 8), p ? phW1 : phW0);
        if (p) phW1 ^= 1; else phW0 ^= 1;

        // two GEMMs (feature s), this warp's n8 tile, K=128 each
        float acc0[4] = {0.f, 0.f, 0.f, 0.f};
        float acc1[4] = {0.f, 0.f, 0.f, 0.f};
        {
            const uint32_t bl = b_base + (uint32_t)(p * WHALF_BYTES);
#pragma unroll
            for (int s = 0; s < 2; ++s) {
                float* acc = s ? acc1 : acc0;
#pragma unroll
                for (int j = 0; j < 4; ++j) {
                    uint32_t b0, b1, b2, b3;
                    asm volatile(
                        "ldmatrix.sync.aligned.m8n8.x4.shared.b16 {%0,%1,%2,%3}, [%4];\n"
                        : "=r"(b0), "=r"(b1), "=r"(b2), "=r"(b3)
                        : "r"(bl + (uint32_t)((s * 128 + j * 32) * 2)));
                    asm volatile(
                        "mma.sync.aligned.m16n8k16.row.col.f32.f16.f16.f32 "
                        "{%0,%1,%2,%3}, {%4,%5,%6,%7}, {%8,%9}, {%0,%1,%2,%3};\n"
                        : "+f"(acc[0]), "+f"(acc[1]), "+f"(acc[2]), "+f"(acc[3])
                        : "r"(a[2*j][0]), "r"(a[2*j][1]), "r"(a[2*j][2]), "r"(a[2*j][3]),
                          "r"(b0), "r"(b1));
                    asm volatile(
                        "mma.sync.aligned.m16n8k16.row.col.f32.f16.f16.f32 "
                        "{%0,%1,%2,%3}, {%4,%5,%6,%7}, {%8,%9}, {%0,%1,%2,%3};\n"
                        : "+f"(acc[0]), "+f"(acc[1]), "+f"(acc[2]), "+f"(acc[3])
                        : "r"(a[2*j+1][0]), "r"(a[2*j+1][1]), "r"(a[2*j+1][2]), "r"(a[2*j+1][3]),
                          "r"(b2), "r"(b3));
                }
            }
        }

        // fold: h += x0[row]*delta0 + x1[row]*delta1  (f32, registers)
        h[0] += cx00 * acc0[0] + cx01 * acc1[0];
        h[1] += cx00 * acc0[1] + cx01 * acc1[1];
        h[2] += cx10 * acc0[2] + cx11 * acc1[2];
        h[3] += cx10 * acc0[3] + cx11 * acc1[3];
        cx00 = nx00; cx01 = nx01; cx10 = nx10; cx11 = nx11;

        if (n + 1 == LSITES) break;   // final h stays in registers

        // publish fp16(h) into next site's A buffer: local + peer (DSMEM)
        {
            const __half2 v0 = __floats2half2_rn(h[0], h[1]);
            const __half2 v1 = __floats2half2_rn(h[2], h[3]);
            const uint32_t e0 = (uint32_t)((1 - p) * ABUF_HALVES + g * AROW + c0g);
            const uint32_t e1 = (uint32_t)((1 - p) * ABUF_HALVES + (g + 8) * AROW + c0g);
            *(__half2*)(Abuf + e0) = v0;
            *(__half2*)(Abuf + e1) = v1;
            asm volatile("st.shared::cluster.b32 [%0], %1;"
                         :: "r"(abuf_peer + e0 * 2), "r"(*(const uint32_t*)&v0) : "memory");
            asm volatile("st.shared::cluster.b32 [%0], %1;"
                         :: "r"(abuf_peer + e1 * 2), "r"(*(const uint32_t*)&v1) : "memory");
        }

        __syncthreads();   // all local+remote publishes issued, local ones visible
        if (tid == 0) {
            // cumulative release: publishes this CTA's remote stores to the peer
            asm volatile("mbarrier.arrive.release.cluster.shared::cluster.b64 _, [%0];"
                         :: "r"(ambar_peer) : "memory");
        }
        mbar_wait_cluster(mb + 16, phA);   // peer's arrive: peer's stores into our Abuf visible
        phA ^= 1;
    }

    // final: assemble full fp32 h in both CTAs (reuse Wbuf[0] region)
    float* Fh = (float*)smem;   // [16][HROW]
    Fh[g * HROW + c0g]           = h[0];
    Fh[g * HROW + c0g + 1]       = h[1];
    Fh[(g + 8) * HROW + c0g]     = h[2];
    Fh[(g + 8) * HROW + c0g + 1] = h[3];
    asm volatile("st.shared::cluster.f32 [%0], %1;"
                 :: "r"(fh_peer + (uint32_t)((g * HROW + c0g) * 4)),       "f"(h[0]) : "memory");
    asm volatile("st.shared::cluster.f32 [%0], %1;"
                 :: "r"(fh_peer + (uint32_t)((g * HROW + c0g + 1) * 4)),   "f"(h[1]) : "memory");
    asm volatile("st.shared::cluster.f32 [%0], %1;"
                 :: "r"(fh_peer + (uint32_t)(((g + 8) * HROW + c0g) * 4)), "f"(h[2]) : "memory");
    asm volatile("st.shared::cluster.f32 [%0], %1;"
                 :: "r"(fh_peer + (uint32_t)(((g + 8) * HROW + c0g + 1) * 4)), "f"(h[3]) : "memory");

    asm volatile("barrier.cluster.arrive.aligned;" ::: "memory");
    asm volatile("barrier.cluster.wait.aligned;"   ::: "memory");

    // classifier: logits = h @ V  (rank 0 writes all 16x10)
    if (rank == 0 && tid < BC * NCLS) {
        int r = tid / NCLS, c = tid % NCLS;
        const float* hr = Fh + r * HROW;
        float s = 0.f;
#pragma unroll 8
        for (int a = 0; a < CHI; ++a) s += hr[a] * __ldg(V + a * NCLS + c);
        out[(size_t)(slab * BC + r) * NCLS + c] = s;
    }
}

// ---------------------------------------------------------------------------
extern "C" void kernel_launch(void* const* d_in, const int* in_sizes, int n_in,
                              void* d_out, int out_size) {
    const float* x = nullptr;  // 1024*2*784    = 1605632
    const float* W = nullptr;  // 784*2*128*128 = 25690112
    const float* V = nullptr;  // 128*10        = 1280
    for (int i = 0; i < n_in; ++i) {
        if (in_sizes[i] == BATCH * 2 * LSITES)            x = (const float*)d_in[i];
        else if (in_sizes[i] == LSITES * 2 * CHI * CHI)   W = (const float*)d_in[i];
        else if (in_sizes[i] == CHI * NCLS)               V = (const float*)d_in[i];
    }
    float* out = (float*)d_out;

    static_assert(SMEM_TOTAL == 76320, "smem layout");

    cudaFuncSetAttribute(prep_kernel, cudaFuncAttributeMaxDynamicSharedMemorySize, SITE_HALVES * 2);
    cudaFuncSetAttribute(mps_kernel,  cudaFuncAttributeMaxDynamicSharedMemorySize, SMEM_TOTAL);

    prep_kernel<<<LSITES, 256, SITE_HALVES * 2>>>(W);
    mps_kernel<<<(BATCH / BC) * 2, 256, SMEM_TOTAL>>>(x, V, out);
    (void)out_size;
}